// round 9
// baseline (speedup 1.0000x reference)
#include <cuda_runtime.h>
#include <math.h>

// Problem constants (fixed by this dataset instance)
constexpr int B = 16, P = 19248, C = 81, G = 16;
constexpr float VAR0 = 0.1f, VAR1 = 0.2f;
constexpr float POS_T = 0.5f, NEG_T = 0.4f;
constexpr int   NPR = 3;
constexpr float BBOX_ALPHA = 1.5f, CONF_ALPHA = 1.0f;

constexpr int TILE = 48;            // priors per k_conf block (48*401 == P exactly)
constexpr int CONF_THREADS = 384;   // 8 threads per prior row
constexpr int NBINS = 2048;         // bits >> 20 (lc >= 0 so sign bit = 0)

// -------- scratch (device globals; no allocation allowed) --------
__device__ unsigned long long g_bestgt[B * G];
__device__ float              g_sl1   [B * P];
__device__ unsigned           g_lcbits[B * P];
__device__ float              g_ce    [B * P];
__device__ unsigned char      g_state [B * P];   // 0=neg, 1=pos, 2=neutral
__device__ int                g_numpos[B];
__device__ unsigned           g_hist  [B * NBINS];
__device__ int                g_hb    [B];
__device__ int                g_r     [B];
__device__ unsigned long long g_cand  [B * P];
__device__ int                g_ccnt  [B];
__device__ unsigned           g_T     [B];
__device__ int                g_cut   [B];
__device__ double             g_acc   [2];
__device__ unsigned           g_done;

// -------- kernel 0: reset --------
__global__ void k_reset() {
    int id = blockIdx.x * 1024 + threadIdx.x;
    if (id < B * NBINS) g_hist[id] = 0u;
    if (blockIdx.x == 0) {
        int t = threadIdx.x;
        if (t < B * G) g_bestgt[t] = 0ULL;
        if (t < B)   { g_numpos[t] = 0; g_ccnt[t] = 0; }
        if (t < 2)     g_acc[t] = 0.0;
        if (t == 0)    g_done = 0u;
    }
}

// -------- kernel 1: per-GT best prior only --------
__global__ void k_match(const float4* __restrict__ priors4,
                        const float* __restrict__ gtb) {
    __shared__ float sg[G * 4];
    __shared__ float sga[G];
    __shared__ unsigned long long sbest[G];
    int b = blockIdx.y;
    int t = threadIdx.x;
    if (t < G * 4) sg[t] = gtb[b * G * 4 + t];
    if (t < G)     sbest[t] = 0ULL;
    __syncthreads();
    if (t < G)     sga[t] = (sg[t*4+2] - sg[t*4+0]) * (sg[t*4+3] - sg[t*4+1]);
    __syncthreads();

    int p = blockIdx.x * blockDim.x + t;
    if (p < P) {
        float4 pr = priors4[(size_t)b * P + p];
        float bx1 = pr.x - 0.5f * pr.z, by1 = pr.y - 0.5f * pr.w;
        float bx2 = pr.x + 0.5f * pr.z, by2 = pr.y + 0.5f * pr.w;
        float areaB = pr.z * pr.w;
        #pragma unroll
        for (int g = 0; g < G; g++) {
            float iw = fmaxf(fminf(sg[g*4+2], bx2) - fmaxf(sg[g*4+0], bx1), 0.0f);
            float ih = fmaxf(fminf(sg[g*4+3], by2) - fmaxf(sg[g*4+1], by1), 0.0f);
            float inter = iw * ih;
            float iou = inter / fmaxf(sga[g] + areaB - inter, 1e-10f);
            unsigned long long key =
                ((unsigned long long)__float_as_uint(iou) << 32) |
                (unsigned long long)(0xFFFFFFFFu - (unsigned)p);  // max iou, then min p
            atomicMax(&sbest[g], key);
        }
    }
    __syncthreads();
    if (t < G) atomicMax(&g_bestgt[b * G + t], sbest[t]);
}

// -------- kernel 2: conf loss pieces + match recompute + force-match + SL1 --------
__global__ __launch_bounds__(CONF_THREADS)
void k_conf(const float* __restrict__ conf,
            const float* __restrict__ loc,
            const float* __restrict__ priors,
            const float* __restrict__ gtb,
            const int*   __restrict__ gtl) {
    __shared__ float sconf[TILE * C];          // 15552 B
    __shared__ int   sbestp[G];
    __shared__ int   slab[G];
    __shared__ float sgb[G * 4];
    __shared__ float sga[G];
    __shared__ int   s_pos[CONF_THREADS / 32];

    int b    = blockIdx.y;
    int tile = blockIdx.x;
    int t    = threadIdx.x;

    if (t < G) {
        unsigned long long key = g_bestgt[b * G + t];
        sbestp[t] = (int)(0xFFFFFFFFu - (unsigned)(key & 0xFFFFFFFFull));
        slab[t]   = gtl[b * G + t];
    }
    if (t < G * 4) sgb[t] = gtb[b * G * 4 + t];

    {
        const float4* src = (const float4*)(conf + ((size_t)b * P + (size_t)tile * TILE) * C);
        float4* dst = (float4*)sconf;
        constexpr int N4 = TILE * C / 4;   // 972
        for (int i = t; i < N4; i += CONF_THREADS) dst[i] = src[i];
    }
    __syncthreads();
    if (t < G) sga[t] = (sgb[t*4+2] - sgb[t*4+0]) * (sgb[t*4+3] - sgb[t*4+1]);
    __syncthreads();

    int row = t >> 3;           // 0..47
    int sub = t & 7;            // 0..7
    const float* srow = sconf + row * C;

    float v[11];
    #pragma unroll
    for (int i = 0; i < 11; i++) {
        int j = sub + i * 8;
        v[i] = (j < C) ? srow[j] : -1e30f;
    }
    float m = v[0];
    #pragma unroll
    for (int i = 1; i < 11; i++) m = fmaxf(m, v[i]);
    m = fmaxf(m, __shfl_xor_sync(0xffffffffu, m, 1));
    m = fmaxf(m, __shfl_xor_sync(0xffffffffu, m, 2));
    m = fmaxf(m, __shfl_xor_sync(0xffffffffu, m, 4));
    float s = 0.0f;
    #pragma unroll
    for (int i = 0; i < 11; i++) s += __expf(v[i] - m);
    s += __shfl_xor_sync(0xffffffffu, s, 1);
    s += __shfl_xor_sync(0xffffffffu, s, 2);
    s += __shfl_xor_sync(0xffffffffu, s, 4);

    bool is_pos = false;
    if (sub == 0) {
        float lse = m + logf(s);
        int p   = tile * TILE + row;
        int idx = b * P + p;
        // recompute per-prior match (bit-identical to k_match arithmetic)
        const float4 pr = *(const float4*)(priors + (size_t)idx * 4);
        float bx1 = pr.x - 0.5f * pr.z, by1 = pr.y - 0.5f * pr.w;
        float bx2 = pr.x + 0.5f * pr.z, by2 = pr.y + 0.5f * pr.w;
        float areaB = pr.z * pr.w;
        float bo = -1.0f; int bi = 0;
        #pragma unroll
        for (int g = 0; g < G; g++) {
            float iw = fmaxf(fminf(sgb[g*4+2], bx2) - fmaxf(sgb[g*4+0], bx1), 0.0f);
            float ih = fmaxf(fminf(sgb[g*4+3], by2) - fmaxf(sgb[g*4+1], by1), 0.0f);
            float inter = iw * ih;
            float iou = inter / fmaxf(sga[g] + areaB - inter, 1e-10f);
            if (iou > bo) { bo = iou; bi = g; }   // first-index argmax
        }
        // force-match (ascending g == sequential scatter, last wins)
        #pragma unroll
        for (int g = 0; g < G; g++)
            if (sbestp[g] == p) { bo = 2.0f; bi = g; }

        int lab = slab[bi];
        int conf_t = (bo < POS_T) ? ((bo < NEG_T) ? 0 : -1) : lab;
        bool pos = conf_t > 0;
        is_pos = pos;
        int tgt = pos ? conf_t : 0;
        float ce = lse - srow[tgt];
        float lc = (pos || conf_t < 0) ? 0.0f : (lse - srow[0]);
        g_ce[idx]     = ce;
        g_lcbits[idx] = __float_as_uint(lc);      // lc >= 0: bits monotonic
        g_state[idx]  = pos ? 1 : (conf_t < 0 ? 2 : 0);
        float sl = 0.0f;
        if (pos) {
            const float4 ld = *(const float4*)(loc + (size_t)idx * 4);
            float gx1 = sgb[bi*4+0], gy1 = sgb[bi*4+1];
            float gx2 = sgb[bi*4+2], gy2 = sgb[bi*4+3];
            float t0 = ((gx1 + gx2) * 0.5f - pr.x) / (VAR0 * pr.z);
            float t1 = ((gy1 + gy2) * 0.5f - pr.y) / (VAR0 * pr.w);
            float t2 = logf(fmaxf((gx2 - gx1) / pr.z, 1e-8f)) / VAR1;
            float t3 = logf(fmaxf((gy2 - gy1) / pr.w, 1e-8f)) / VAR1;
            float d;
            d = ld.x - t0; sl += (fabsf(d) < 1.0f) ? 0.5f * d * d : fabsf(d) - 0.5f;
            d = ld.y - t1; sl += (fabsf(d) < 1.0f) ? 0.5f * d * d : fabsf(d) - 0.5f;
            d = ld.z - t2; sl += (fabsf(d) < 1.0f) ? 0.5f * d * d : fabsf(d) - 0.5f;
            d = ld.w - t3; sl += (fabsf(d) < 1.0f) ? 0.5f * d * d : fabsf(d) - 0.5f;
        }
        g_sl1[idx] = sl;
    }
    unsigned bal = __ballot_sync(0xffffffffu, is_pos);
    if ((t & 31) == 0) s_pos[t >> 5] = __popc(bal);
    __syncthreads();
    if (t == 0) {
        int c = 0;
        #pragma unroll
        for (int w = 0; w < CONF_THREADS / 32; w++) c += s_pos[w];
        if (c) atomicAdd(&g_numpos[b], c);
    }
}

// -------- kernel 3: smem-staged per-image histogram (2048 bins, bits>>20) --------
__global__ __launch_bounds__(1024)
void k_hist() {
    __shared__ unsigned sh[NBINS];
    int b = blockIdx.y;
    int t = threadIdx.x;
    sh[t] = 0u; sh[t + 1024] = 0u;
    __syncthreads();
    int p = blockIdx.x * 1024 + t;
    if (p < P) atomicAdd(&sh[g_lcbits[b * P + p] >> 20], 1u);
    __syncthreads();
    unsigned c0 = sh[t], c1 = sh[t + 1024];
    if (c0) atomicAdd(&g_hist[b * NBINS + t], c0);
    if (c1) atomicAdd(&g_hist[b * NBINS + t + 1024], c1);
}

// -------- kernel 4: boundary bin from 2048-bin histogram (no data pass) --------
__global__ __launch_bounds__(1024)
void k_thresh() {
    int b = blockIdx.x;
    int t = threadIdx.x;
    __shared__ int sc[1024];
    const unsigned* h = g_hist + b * NBINS;

    int k = NPR * g_numpos[b];
    if (k > P - 1) k = P - 1;

    int c0 = (int)h[2 * t], c1 = (int)h[2 * t + 1];
    sc[t] = c0 + c1;
    __syncthreads();
    // suffix sums over 1024 chunks of 2 bins
    for (int off = 1; off < 1024; off <<= 1) {
        int add = (t + off < 1024) ? sc[t + off] : 0;
        __syncthreads();
        sc[t] += add;
        __syncthreads();
    }
    int above_chunk = (t + 1 < 1024) ? sc[t + 1] : 0;
    if (above_chunk < k && k <= sc[t]) {
        if (k <= above_chunk + c1) {        // high bin of the pair first
            g_hb[b] = 2 * t + 1;
            g_r[b]  = k - above_chunk;
        } else {
            g_hb[b] = 2 * t;
            g_r[b]  = k - above_chunk - c1;
        }
    }
}

// -------- kernel 5: gather candidates in boundary bin --------
__global__ __launch_bounds__(1024)
void k_gather() {
    int b = blockIdx.y;
    int p = blockIdx.x * 1024 + threadIdx.x;
    if (p < P) {
        unsigned bits = g_lcbits[b * P + p];
        if ((int)(bits >> 20) == g_hb[b]) {
            int pos = atomicAdd(&g_ccnt[b], 1);
            g_cand[b * P + pos] =
                ((unsigned long long)bits << 32) |
                (unsigned long long)(0xFFFFFFFFu - (unsigned)p); // bits desc, p asc
        }
    }
}

// -------- kernel 6: exact r-th largest among candidates --------
__global__ __launch_bounds__(256)
void k_pick() {
    int b = blockIdx.x;
    int t = threadIdx.x;
    __shared__ unsigned long long stage[2048];
    const unsigned long long* cand = g_cand + b * P;
    int n = g_ccnt[b];
    int r = g_r[b];

    int cnt[4];
    unsigned long long own[4];
    int nown = 0;
    for (int i = t; i < n && nown < 4; i += 256) { own[nown] = cand[i]; cnt[nown] = 0; nown++; }
    bool big = (n > 1024);

    for (int base = 0; base < n; base += 2048) {
        int mm = min(2048, n - base);
        for (int i = t; i < mm; i += 256) stage[i] = cand[base + i];
        __syncthreads();
        for (int o = 0; o < nown; o++) {
            unsigned long long key = own[o];
            for (int i = 0; i < mm; i++)
                if (stage[i] > key) cnt[o]++;
        }
        __syncthreads();
    }
    for (int o = 0; o < nown; o++) {
        if (cnt[o] == r - 1) {
            g_T[b]   = (unsigned)(own[o] >> 32);
            g_cut[b] = (int)(0xFFFFFFFFu - (unsigned)(own[o] & 0xFFFFFFFFull));
        }
    }
    if (big) {   // safety fallback for huge tie sets
        for (int i = t + 1024; i < n; i += 256) {
            unsigned long long key = cand[i];
            int c = 0;
            for (int j = 0; j < n; j++) if (cand[j] > key) c++;
            if (c == r - 1) {
                g_T[b]   = (unsigned)(key >> 32);
                g_cut[b] = (int)(0xFFFFFFFFu - (unsigned)(key & 0xFFFFFFFFull));
            }
        }
    }
}

// -------- kernel 7: final masked sums + output --------
__global__ __launch_bounds__(256)
void k_final(float* __restrict__ out) {
    int b = blockIdx.y;
    int p = blockIdx.x * 256 + threadIdx.x;
    float cB = 0.0f, cC = 0.0f;
    if (p < P) {
        int idx = b * P + p;
        int st = g_state[idx];
        unsigned bits = g_lcbits[idx];
        unsigned T = g_T[b];
        int cut = g_cut[b];
        bool neg = (st == 0) && (bits > T || (bits == T && p <= cut));
        bool pos = (st == 1);
        if (pos) cB = g_sl1[idx] / (float)max(g_numpos[b], 1);
        if (pos || neg) cC = g_ce[idx];
    }
    #pragma unroll
    for (int o = 16; o > 0; o >>= 1) {
        cB += __shfl_xor_sync(0xffffffffu, cB, o);
        cC += __shfl_xor_sync(0xffffffffu, cC, o);
    }
    __shared__ float sB[8], sC[8];
    int w = threadIdx.x >> 5;
    if ((threadIdx.x & 31) == 0) { sB[w] = cB; sC[w] = cC; }
    __syncthreads();
    if (threadIdx.x == 0) {
        float tB = 0.0f, tC = 0.0f;
        #pragma unroll
        for (int i = 0; i < 8; i++) { tB += sB[i]; tC += sC[i]; }
        if (tB != 0.0f) atomicAdd(&g_acc[0], (double)tB);
        if (tC != 0.0f) atomicAdd(&g_acc[1], (double)tC);
        __threadfence();
        unsigned old = atomicAdd(&g_done, 1u);
        if (old == gridDim.x * gridDim.y - 1) {
            out[0] = (float)(g_acc[0] * (double)BBOX_ALPHA / (double)B);
            out[1] = (float)(g_acc[1] * (double)CONF_ALPHA / (double)B);
        }
    }
}

extern "C" void kernel_launch(void* const* d_in, const int* in_sizes, int n_in,
                              void* d_out, int out_size) {
    const float* loc    = (const float*)d_in[0];
    const float* conf   = (const float*)d_in[1];
    const float* priors = (const float*)d_in[2];
    const float* gtb    = (const float*)d_in[3];
    const int*   gtl    = (const int*)d_in[4];
    float* out = (float*)d_out;

    k_reset<<<(B * NBINS + 1023) / 1024, 1024>>>();
    {
        dim3 grid((P + 255) / 256, B);
        k_match<<<grid, 256>>>((const float4*)priors, gtb);
    }
    {
        dim3 grid(P / TILE, B);   // 401 x 16
        k_conf<<<grid, CONF_THREADS>>>(conf, loc, priors, gtb, gtl);
    }
    {
        dim3 grid((P + 1023) / 1024, B);
        k_hist<<<grid, 1024>>>();
    }
    k_thresh<<<B, 1024>>>();
    {
        dim3 grid((P + 1023) / 1024, B);
        k_gather<<<grid, 1024>>>();
    }
    k_pick<<<B, 256>>>();
    {
        dim3 grid((P + 255) / 256, B);
        k_final<<<grid, 256>>>(out);
    }
}

// round 11
// speedup vs baseline: 2.3060x; 2.3060x over previous
#include <cuda_runtime.h>
#include <math.h>

// Problem constants (fixed by this dataset instance)
constexpr int B = 16, P = 19248, C = 81, G = 16;
constexpr float VAR0 = 0.1f, VAR1 = 0.2f;
constexpr float POS_T = 0.5f, NEG_T = 0.4f;
constexpr int   NPR = 3;
constexpr float BBOX_ALPHA = 1.5f, CONF_ALPHA = 1.0f;

constexpr int TILE = 48;            // priors per k_conf block (48*401 == P exactly)
constexpr int CONF_THREADS = 384;   // 8 threads per prior row
constexpr int NB1 = 2048;           // bits >> 20   (bit31 == 0 since lc >= 0)
constexpr int NB2 = 1024;           // (bits >> 10) & 0x3FF
constexpr int NB3 = 1024;           // bits & 0x3FF

// -------- scratch (device globals; no allocation allowed) --------
__device__ unsigned long long g_bestgt[B * G];
__device__ float              g_sl1   [B * P];
__device__ unsigned           g_lcbits[B * P];
__device__ float              g_ce    [B * P];
__device__ unsigned char      g_state [B * P];   // 0=neg, 1=pos, 2=neutral
__device__ int                g_numpos[B];
__device__ unsigned           g_h1    [B * NB1];
__device__ unsigned           g_h2    [B * NB2];
__device__ unsigned           g_h3    [B * NB3];
__device__ int                g_hb1   [B];
__device__ int                g_hb2   [B];
__device__ int                g_r1    [B];
__device__ int                g_r2    [B];
__device__ int                g_r3    [B];
__device__ unsigned           g_T     [B];
__device__ int                g_cut   [B];
__device__ double             g_acc   [2];
__device__ unsigned           g_done;

// -------- kernel 0: reset --------
__global__ void k_reset() {
    int id = blockIdx.x * 1024 + threadIdx.x;
    if (id < B * NB1) g_h1[id] = 0u;
    else if (id < B * NB1 + B * NB2) g_h2[id - B * NB1] = 0u;
    else if (id < B * NB1 + B * NB2 + B * NB3) g_h3[id - B * NB1 - B * NB2] = 0u;
    if (blockIdx.x == 0) {
        int t = threadIdx.x;
        if (t < B * G) g_bestgt[t] = 0ULL;
        if (t < B)     g_numpos[t] = 0;
        if (t < 2)     g_acc[t] = 0.0;
        if (t == 0)    g_done = 0u;
    }
}

// -------- kernel 1: per-GT best prior only --------
__global__ void k_match(const float4* __restrict__ priors4,
                        const float* __restrict__ gtb) {
    __shared__ float sg[G * 4];
    __shared__ float sga[G];
    __shared__ unsigned long long sbest[G];
    int b = blockIdx.y;
    int t = threadIdx.x;
    if (t < G * 4) sg[t] = gtb[b * G * 4 + t];
    if (t < G)     sbest[t] = 0ULL;
    __syncthreads();
    if (t < G)     sga[t] = (sg[t*4+2] - sg[t*4+0]) * (sg[t*4+3] - sg[t*4+1]);
    __syncthreads();

    int p = blockIdx.x * blockDim.x + t;
    if (p < P) {
        float4 pr = priors4[(size_t)b * P + p];
        float bx1 = pr.x - 0.5f * pr.z, by1 = pr.y - 0.5f * pr.w;
        float bx2 = pr.x + 0.5f * pr.z, by2 = pr.y + 0.5f * pr.w;
        float areaB = pr.z * pr.w;
        #pragma unroll
        for (int g = 0; g < G; g++) {
            float iw = fmaxf(fminf(sg[g*4+2], bx2) - fmaxf(sg[g*4+0], bx1), 0.0f);
            float ih = fmaxf(fminf(sg[g*4+3], by2) - fmaxf(sg[g*4+1], by1), 0.0f);
            float inter = iw * ih;
            float iou = inter / fmaxf(sga[g] + areaB - inter, 1e-10f);
            unsigned long long key =
                ((unsigned long long)__float_as_uint(iou) << 32) |
                (unsigned long long)(0xFFFFFFFFu - (unsigned)p);  // max iou, then min p
            atomicMax(&sbest[g], key);
        }
    }
    __syncthreads();
    if (t < G) atomicMax(&g_bestgt[b * G + t], sbest[t]);
}

// -------- kernel 2: conf loss pieces + match recompute + force-match + SL1 --------
__global__ __launch_bounds__(CONF_THREADS)
void k_conf(const float* __restrict__ conf,
            const float* __restrict__ loc,
            const float* __restrict__ priors,
            const float* __restrict__ gtb,
            const int*   __restrict__ gtl) {
    __shared__ float sconf[TILE * C];          // 15552 B
    __shared__ int   sbestp[G];
    __shared__ int   slab[G];
    __shared__ float sgb[G * 4];
    __shared__ float sga[G];
    __shared__ int   s_pos[CONF_THREADS / 32];

    int b    = blockIdx.y;
    int tile = blockIdx.x;
    int t    = threadIdx.x;

    if (t < G) {
        unsigned long long key = g_bestgt[b * G + t];
        sbestp[t] = (int)(0xFFFFFFFFu - (unsigned)(key & 0xFFFFFFFFull));
        slab[t]   = gtl[b * G + t];
    }
    if (t < G * 4) sgb[t] = gtb[b * G * 4 + t];

    {
        const float4* src = (const float4*)(conf + ((size_t)b * P + (size_t)tile * TILE) * C);
        float4* dst = (float4*)sconf;
        constexpr int N4 = TILE * C / 4;   // 972
        for (int i = t; i < N4; i += CONF_THREADS) dst[i] = src[i];
    }
    __syncthreads();
    if (t < G) sga[t] = (sgb[t*4+2] - sgb[t*4+0]) * (sgb[t*4+3] - sgb[t*4+1]);
    __syncthreads();

    int row = t >> 3;           // 0..47
    int sub = t & 7;            // 0..7
    const float* srow = sconf + row * C;

    float v[11];
    #pragma unroll
    for (int i = 0; i < 11; i++) {
        int j = sub + i * 8;
        v[i] = (j < C) ? srow[j] : -1e30f;
    }
    float m = v[0];
    #pragma unroll
    for (int i = 1; i < 11; i++) m = fmaxf(m, v[i]);
    m = fmaxf(m, __shfl_xor_sync(0xffffffffu, m, 1));
    m = fmaxf(m, __shfl_xor_sync(0xffffffffu, m, 2));
    m = fmaxf(m, __shfl_xor_sync(0xffffffffu, m, 4));
    float s = 0.0f;
    #pragma unroll
    for (int i = 0; i < 11; i++) s += __expf(v[i] - m);
    s += __shfl_xor_sync(0xffffffffu, s, 1);
    s += __shfl_xor_sync(0xffffffffu, s, 2);
    s += __shfl_xor_sync(0xffffffffu, s, 4);

    bool is_pos = false;
    if (sub == 0) {
        float lse = m + logf(s);
        int p   = tile * TILE + row;
        int idx = b * P + p;
        // recompute per-prior match (bit-identical to k_match arithmetic)
        const float4 pr = *(const float4*)(priors + (size_t)idx * 4);
        float bx1 = pr.x - 0.5f * pr.z, by1 = pr.y - 0.5f * pr.w;
        float bx2 = pr.x + 0.5f * pr.z, by2 = pr.y + 0.5f * pr.w;
        float areaB = pr.z * pr.w;
        float bo = -1.0f; int bi = 0;
        #pragma unroll
        for (int g = 0; g < G; g++) {
            float iw = fmaxf(fminf(sgb[g*4+2], bx2) - fmaxf(sgb[g*4+0], bx1), 0.0f);
            float ih = fmaxf(fminf(sgb[g*4+3], by2) - fmaxf(sgb[g*4+1], by1), 0.0f);
            float inter = iw * ih;
            float iou = inter / fmaxf(sga[g] + areaB - inter, 1e-10f);
            if (iou > bo) { bo = iou; bi = g; }   // first-index argmax
        }
        // force-match (ascending g == sequential scatter, last wins)
        #pragma unroll
        for (int g = 0; g < G; g++)
            if (sbestp[g] == p) { bo = 2.0f; bi = g; }

        int lab = slab[bi];
        int conf_t = (bo < POS_T) ? ((bo < NEG_T) ? 0 : -1) : lab;
        bool pos = conf_t > 0;
        is_pos = pos;
        int tgt = pos ? conf_t : 0;
        float ce = lse - srow[tgt];
        float lc = (pos || conf_t < 0) ? 0.0f : (lse - srow[0]);
        g_ce[idx]     = ce;
        g_lcbits[idx] = __float_as_uint(lc);      // lc >= 0: bits monotonic
        g_state[idx]  = pos ? 1 : (conf_t < 0 ? 2 : 0);
        float sl = 0.0f;
        if (pos) {
            const float4 ld = *(const float4*)(loc + (size_t)idx * 4);
            float gx1 = sgb[bi*4+0], gy1 = sgb[bi*4+1];
            float gx2 = sgb[bi*4+2], gy2 = sgb[bi*4+3];
            float t0 = ((gx1 + gx2) * 0.5f - pr.x) / (VAR0 * pr.z);
            float t1 = ((gy1 + gy2) * 0.5f - pr.y) / (VAR0 * pr.w);
            float t2 = logf(fmaxf((gx2 - gx1) / pr.z, 1e-8f)) / VAR1;
            float t3 = logf(fmaxf((gy2 - gy1) / pr.w, 1e-8f)) / VAR1;
            float d;
            d = ld.x - t0; sl += (fabsf(d) < 1.0f) ? 0.5f * d * d : fabsf(d) - 0.5f;
            d = ld.y - t1; sl += (fabsf(d) < 1.0f) ? 0.5f * d * d : fabsf(d) - 0.5f;
            d = ld.z - t2; sl += (fabsf(d) < 1.0f) ? 0.5f * d * d : fabsf(d) - 0.5f;
            d = ld.w - t3; sl += (fabsf(d) < 1.0f) ? 0.5f * d * d : fabsf(d) - 0.5f;
        }
        g_sl1[idx] = sl;
    }
    unsigned bal = __ballot_sync(0xffffffffu, is_pos);
    if ((t & 31) == 0) s_pos[t >> 5] = __popc(bal);
    __syncthreads();
    if (t == 0) {
        int c = 0;
        #pragma unroll
        for (int w = 0; w < CONF_THREADS / 32; w++) c += s_pos[w];
        if (c) atomicAdd(&g_numpos[b], c);
    }
}

// -------- kernel 3: smem-staged level-1 histogram (2048 bins, bits>>20) --------
__global__ __launch_bounds__(1024)
void k_hist1() {
    __shared__ unsigned sh[NB1];
    int b = blockIdx.y;
    int t = threadIdx.x;
    sh[t] = 0u; sh[t + 1024] = 0u;
    __syncthreads();
    int p = blockIdx.x * 1024 + t;
    if (p < P) atomicAdd(&sh[g_lcbits[b * P + p] >> 20], 1u);
    __syncthreads();
    unsigned c0 = sh[t], c1 = sh[t + 1024];
    if (c0) atomicAdd(&g_h1[b * NB1 + t], c0);
    if (c1) atomicAdd(&g_h1[b * NB1 + t + 1024], c1);
}

// ---- shuffle-based block suffix sum (1024 threads): returns sum_{j>=t} c_j ----
__device__ __forceinline__ int block_suffix_incl(int c, int t, int* wsmem) {
    int lane = t & 31, w = t >> 5;
    int v = c;
    #pragma unroll
    for (int off = 1; off < 32; off <<= 1) {
        int u = __shfl_down_sync(0xffffffffu, v, off);
        if (lane + off < 32) v += u;
    }
    if (lane == 0) wsmem[w] = v;   // warp total
    __syncthreads();
    if (t < 32) {
        int x = wsmem[t];
        #pragma unroll
        for (int off = 1; off < 32; off <<= 1) {
            int u = __shfl_down_sync(0xffffffffu, x, off);
            if (t + off < 32) x += u;
        }
        wsmem[t] = x;              // suffix of warp totals, incl own warp
    }
    __syncthreads();
    int add = (w + 1 < 32) ? wsmem[w + 1] : 0;
    return v + add;
}

// -------- kernel 4: level-1 boundary (2 bins/thread) --------
__global__ __launch_bounds__(1024)
void k_sel1() {
    __shared__ int wsmem[32];
    int b = blockIdx.x, t = threadIdx.x;
    const unsigned* h = g_h1 + b * NB1;
    int k = NPR * g_numpos[b];
    if (k > P - 1) k = P - 1;
    int c0 = (int)h[2 * t], c1 = (int)h[2 * t + 1];
    int S = block_suffix_incl(c0 + c1, t, wsmem);
    int above = S - c0 - c1;       // suffix starting after this thread's pair
    // high bin of the pair first (descending value order)
    if (above < k && k <= above + c1) { g_hb1[b] = 2 * t + 1; g_r1[b] = k - above; }
    else if (above + c1 < k && k <= above + c1 + c0) { g_hb1[b] = 2 * t; g_r1[b] = k - above - c1; }
}

// -------- kernel 5: level-2 histogram (predicated) --------
__global__ __launch_bounds__(1024)
void k_hist2() {
    int b = blockIdx.y;
    int p = blockIdx.x * 1024 + threadIdx.x;
    if (p < P) {
        unsigned bits = g_lcbits[b * P + p];
        if ((int)(bits >> 20) == g_hb1[b])
            atomicAdd(&g_h2[b * NB2 + ((bits >> 10) & 0x3FFu)], 1u);
    }
}

// -------- kernel 6: level-2 boundary (1 bin/thread) --------
__global__ __launch_bounds__(1024)
void k_sel2() {
    __shared__ int wsmem[32];
    int b = blockIdx.x, t = threadIdx.x;
    int c = (int)g_h2[b * NB2 + t];
    int k = g_r1[b];
    int S = block_suffix_incl(c, t, wsmem);
    int above = S - c;
    if (above < k && k <= above + c) { g_hb2[b] = t; g_r2[b] = k - above; }
}

// -------- kernel 7: level-3 histogram (predicated on top 22 bits) --------
__global__ __launch_bounds__(1024)
void k_hist3() {
    int b = blockIdx.y;
    int p = blockIdx.x * 1024 + threadIdx.x;
    if (p < P) {
        unsigned bits = g_lcbits[b * P + p];
        unsigned pref = ((unsigned)g_hb1[b] << 10) | (unsigned)g_hb2[b];
        if ((bits >> 10) == pref)
            atomicAdd(&g_h3[b * NB3 + (bits & 0x3FFu)], 1u);
    }
}

// -------- kernel 8: level-3 boundary -> exact threshold bits T + tie rank r3 --------
__global__ __launch_bounds__(1024)
void k_sel3() {
    __shared__ int wsmem[32];
    int b = blockIdx.x, t = threadIdx.x;
    int c = (int)g_h3[b * NB3 + t];
    int k = g_r2[b];
    int S = block_suffix_incl(c, t, wsmem);
    int above = S - c;
    if (above < k && k <= above + c) {
        g_T[b]  = ((unsigned)g_hb1[b] << 20) | ((unsigned)g_hb2[b] << 10) | (unsigned)t;
        g_r3[b] = k - above;
    }
}

// -------- kernel 9: tie cutoff index (r3-th occurrence of bits==T, index order) --------
__global__ __launch_bounds__(1024)
void k_cut() {
    __shared__ int wsmem[32];
    int b = blockIdx.x, t = threadIdx.x;
    unsigned T = g_T[b];
    int r = g_r3[b];
    const unsigned* lc = g_lcbits + b * P;
    constexpr int CHUNK = (P + 1023) / 1024;   // 19
    int beg = t * CHUNK;
    int end = min(beg + CHUNK, P);
    int cnt = 0;
    for (int p = beg; p < end; p++) cnt += (lc[p] == T);
    // exclusive prefix sum over 1024 chunk counts
    int lane = t & 31, w = t >> 5;
    int v = cnt;
    #pragma unroll
    for (int off = 1; off < 32; off <<= 1) {
        int u = __shfl_up_sync(0xffffffffu, v, off);
        if (lane >= off) v += u;
    }
    if (lane == 31) wsmem[w] = v;   // warp total
    __syncthreads();
    if (t < 32) {
        int x = wsmem[t];
        #pragma unroll
        for (int off = 1; off < 32; off <<= 1) {
            int u = __shfl_up_sync(0xffffffffu, x, off);
            if (t >= off) x += u;
        }
        wsmem[t] = x;               // inclusive prefix of warp totals
    }
    __syncthreads();
    int excl = ((w > 0) ? wsmem[w - 1] : 0) + v - cnt;
    if (excl < r && r <= excl + cnt) {
        int want = r - excl;
        for (int p = beg; p < end; p++) {
            if (lc[p] == T && --want == 0) { g_cut[b] = p; break; }
        }
    }
}

// -------- kernel 10: final masked sums + output --------
__global__ __launch_bounds__(256)
void k_final(float* __restrict__ out) {
    int b = blockIdx.y;
    int p = blockIdx.x * 256 + threadIdx.x;
    float cB = 0.0f, cC = 0.0f;
    if (p < P) {
        int idx = b * P + p;
        int st = g_state[idx];
        unsigned bits = g_lcbits[idx];
        unsigned T = g_T[b];
        int cut = g_cut[b];
        bool neg = (st == 0) && (bits > T || (bits == T && p <= cut));
        bool pos = (st == 1);
        if (pos) cB = g_sl1[idx] / (float)max(g_numpos[b], 1);
        if (pos || neg) cC = g_ce[idx];
    }
    #pragma unroll
    for (int o = 16; o > 0; o >>= 1) {
        cB += __shfl_xor_sync(0xffffffffu, cB, o);
        cC += __shfl_xor_sync(0xffffffffu, cC, o);
    }
    __shared__ float sB[8], sC[8];
    int w = threadIdx.x >> 5;
    if ((threadIdx.x & 31) == 0) { sB[w] = cB; sC[w] = cC; }
    __syncthreads();
    if (threadIdx.x == 0) {
        float tB = 0.0f, tC = 0.0f;
        #pragma unroll
        for (int i = 0; i < 8; i++) { tB += sB[i]; tC += sC[i]; }
        if (tB != 0.0f) atomicAdd(&g_acc[0], (double)tB);
        if (tC != 0.0f) atomicAdd(&g_acc[1], (double)tC);
        __threadfence();
        unsigned old = atomicAdd(&g_done, 1u);
        if (old == gridDim.x * gridDim.y - 1) {
            out[0] = (float)(g_acc[0] * (double)BBOX_ALPHA / (double)B);
            out[1] = (float)(g_acc[1] * (double)CONF_ALPHA / (double)B);
        }
    }
}

extern "C" void kernel_launch(void* const* d_in, const int* in_sizes, int n_in,
                              void* d_out, int out_size) {
    const float* loc    = (const float*)d_in[0];
    const float* conf   = (const float*)d_in[1];
    const float* priors = (const float*)d_in[2];
    const float* gtb    = (const float*)d_in[3];
    const int*   gtl    = (const int*)d_in[4];
    float* out = (float*)d_out;

    k_reset<<<(B * (NB1 + NB2 + NB3) + 1023) / 1024, 1024>>>();
    {
        dim3 grid((P + 255) / 256, B);
        k_match<<<grid, 256>>>((const float4*)priors, gtb);
    }
    {
        dim3 grid(P / TILE, B);   // 401 x 16
        k_conf<<<grid, CONF_THREADS>>>(conf, loc, priors, gtb, gtl);
    }
    dim3 gridP((P + 1023) / 1024, B);
    k_hist1<<<gridP, 1024>>>();
    k_sel1<<<B, 1024>>>();
    k_hist2<<<gridP, 1024>>>();
    k_sel2<<<B, 1024>>>();
    k_hist3<<<gridP, 1024>>>();
    k_sel3<<<B, 1024>>>();
    k_cut<<<B, 1024>>>();
    {
        dim3 grid((P + 255) / 256, B);
        k_final<<<grid, 256>>>(out);
    }
}